// round 1
// baseline (speedup 1.0000x reference)
#include <cuda_runtime.h>

#define N_NODES 100000
#define N_EDGES 800000
#define DIM     64
#define HEADS   4
#define DH      16

// L2-resident scratch (GB300 L2 = ~126MB; Q+K+V = 76.8MB)
__device__ float g_Q[N_NODES * DIM];
__device__ float g_K[N_NODES * DIM];
__device__ float g_V[N_NODES * DIM];
__device__ float g_norm[N_NODES * HEADS];

// ---------------------------------------------------------------------------
// Zero the res region of d_out and the norm accumulator.
// ---------------------------------------------------------------------------
__global__ void zero_kernel(float* __restrict__ res) {
    int i = blockIdx.x * blockDim.x + threadIdx.x;
    if (i < N_NODES * DIM)   res[i]    = 0.0f;
    if (i < N_NODES * HEADS) g_norm[i] = 0.0f;
}

// ---------------------------------------------------------------------------
// O[n, :] = E[n, :] @ W  for a 64-node tile per block. W and E tile in smem.
// 256 threads: thread t handles node (t>>2) of the tile, output cols
// [(t&3)*16, (t&3)*16+16).
// ---------------------------------------------------------------------------
__global__ void gemm64(const float* __restrict__ E, const float* __restrict__ W,
                       float* __restrict__ O) {
    __shared__ float sW[64 * 64];
    __shared__ float sE[64 * 65];   // +1 pad to dodge bank conflicts on row reads

    int t = threadIdx.x;
    int base = blockIdx.x * 64;

    #pragma unroll
    for (int i = 0; i < 16; i++) sW[t + i * 256] = W[t + i * 256];

    for (int i = t; i < 64 * 64; i += 256) {
        int r = i >> 6, c = i & 63;
        int node = base + r;
        sE[r * 65 + c] = (node < N_NODES) ? E[node * 64 + c] : 0.0f;
    }
    __syncthreads();

    int nl = t >> 2;
    int q  = (t & 3) * 16;

    float acc[16];
    #pragma unroll
    for (int j = 0; j < 16; j++) acc[j] = 0.0f;

    #pragma unroll 4
    for (int k = 0; k < 64; k++) {
        float e = sE[nl * 65 + k];
        #pragma unroll
        for (int j = 0; j < 16; j++)
            acc[j] = fmaf(e, sW[k * 64 + q + j], acc[j]);
    }

    int node = base + nl;
    if (node < N_NODES) {
        float4* o = (float4*)(O + node * 64 + q);
        o[0] = make_float4(acc[0],  acc[1],  acc[2],  acc[3]);
        o[1] = make_float4(acc[4],  acc[5],  acc[6],  acc[7]);
        o[2] = make_float4(acc[8],  acc[9],  acc[10], acc[11]);
        o[3] = make_float4(acc[12], acc[13], acc[14], acc[15]);
    }
}

// ---------------------------------------------------------------------------
// Pass 1: expAtt[e,h] = exp(clip(q·k, -10, 10)); accumulate segment norms.
// One thread per (edge, head).
// ---------------------------------------------------------------------------
__global__ void edge_logits(const int* __restrict__ rows, const int* __restrict__ cols,
                            float* __restrict__ att) {
    int idx = blockIdx.x * blockDim.x + threadIdx.x;
    if (idx >= N_EDGES * HEADS) return;
    int e = idx >> 2, h = idx & 3;
    int r = rows[e], c = cols[e];

    const float4* q = (const float4*)(g_Q + r * DIM + h * DH);
    const float4* k = (const float4*)(g_K + c * DIM + h * DH);

    float s = 0.0f;
    #pragma unroll
    for (int i = 0; i < 4; i++) {
        float4 a = q[i], b = k[i];
        s += a.x * b.x + a.y * b.y + a.z * b.z + a.w * b.w;
    }
    s = fminf(fmaxf(s, -10.0f), 10.0f);
    float ex = expf(s);

    att[idx] = ex;                               // staged; normalized in pass 2
    atomicAdd(&g_norm[r * HEADS + h], ex);
}

// ---------------------------------------------------------------------------
// Vector reduction (no return): 1 L2 transaction for 4 floats. sm_90+.
// ---------------------------------------------------------------------------
__device__ __forceinline__ void red_add_v4(float* addr, float a, float b,
                                           float c, float d) {
    asm volatile("red.global.add.v4.f32 [%0], {%1, %2, %3, %4};"
                 :: "l"(addr), "f"(a), "f"(b), "f"(c), "f"(d)
                 : "memory");
}

// ---------------------------------------------------------------------------
// Pass 2: att = expAtt / (norm[row] + eps); res[row] += att * V[col].
// One thread per (edge, head); 4 vector-REDs per thread.
// ---------------------------------------------------------------------------
__global__ void edge_accum(const int* __restrict__ rows, const int* __restrict__ cols,
                           float* __restrict__ res, float* __restrict__ att) {
    int idx = blockIdx.x * blockDim.x + threadIdx.x;
    if (idx >= N_EDGES * HEADS) return;
    int e = idx >> 2, h = idx & 3;
    int r = rows[e], c = cols[e];

    float ex = att[idx];
    float a  = ex / (g_norm[r * HEADS + h] + 1e-8f);
    att[idx] = a;

    const float4* v = (const float4*)(g_V + c * DIM + h * DH);
    float* dst = res + r * DIM + h * DH;
    #pragma unroll
    for (int i = 0; i < 4; i++) {
        float4 vv = v[i];
        red_add_v4(dst + i * 4, a * vv.x, a * vv.y, a * vv.z, a * vv.w);
    }
}

// ---------------------------------------------------------------------------
extern "C" void kernel_launch(void* const* d_in, const int* in_sizes, int n_in,
                              void* d_out, int out_size) {
    const float* embeds = (const float*)d_in[0];
    const float* Wq     = (const float*)d_in[1];
    const float* Wk     = (const float*)d_in[2];
    const float* Wv     = (const float*)d_in[3];
    const int*   rows   = (const int*)d_in[4];
    const int*   cols   = (const int*)d_in[5];

    float* res = (float*)d_out;                    // [N_NODES, 64]
    float* att = (float*)d_out + N_NODES * DIM;    // [N_EDGES, 4]

    void *pQ, *pK, *pV;
    cudaGetSymbolAddress(&pQ, g_Q);
    cudaGetSymbolAddress(&pK, g_K);
    cudaGetSymbolAddress(&pV, g_V);

    // 1) zero res + norm
    zero_kernel<<<(N_NODES * DIM + 255) / 256, 256>>>(res);

    // 2) QKV projections (per node, not per edge)
    int gemm_blocks = (N_NODES + 63) / 64;
    gemm64<<<gemm_blocks, 256>>>(embeds, Wq, (float*)pQ);
    gemm64<<<gemm_blocks, 256>>>(embeds, Wk, (float*)pK);
    gemm64<<<gemm_blocks, 256>>>(embeds, Wv, (float*)pV);

    // 3) logits + segment norm
    int edge_blocks = (N_EDGES * HEADS + 255) / 256;
    edge_logits<<<edge_blocks, 256>>>(rows, cols, att);

    // 4) normalize + scatter-accumulate
    edge_accum<<<edge_blocks, 256>>>(rows, cols, res, att);
}

// round 2
// speedup vs baseline: 1.0594x; 1.0594x over previous
#include <cuda_runtime.h>

#define N_NODES 100000
#define N_EDGES 800000
#define DIM     64
#define HEADS   4
#define DH      16

typedef unsigned long long u64;
typedef unsigned int       u32;

// L2-resident scratch (GB300 L2 ~126MB; Q+K+V = 76.8MB)
__device__ float g_Q[N_NODES * DIM];
__device__ float g_K[N_NODES * DIM];
__device__ float g_V[N_NODES * DIM];
__device__ float g_norm[N_NODES * HEADS];

// ---------------------------------------------------------------------------
// Packed fp32x2 FMA (Blackwell FFMA2) — 2 lane-FMAs per instruction.
// ---------------------------------------------------------------------------
__device__ __forceinline__ u64 ffma2(u64 a, u64 b, u64 c) {
    u64 d;
    asm("fma.rn.f32x2 %0, %1, %2, %3;" : "=l"(d) : "l"(a), "l"(b), "l"(c));
    return d;
}
__device__ __forceinline__ u64 pack2(float x) {
    u64 r; u32 xi = __float_as_uint(x);
    asm("mov.b64 %0, {%1, %1};" : "=l"(r) : "r"(xi));
    return r;
}

// ---------------------------------------------------------------------------
// Zero the res region of d_out and the norm accumulator.
// ---------------------------------------------------------------------------
__global__ void zero_kernel(float* __restrict__ res) {
    int i = blockIdx.x * blockDim.x + threadIdx.x;
    if (i < N_NODES * DIM)   res[i]    = 0.0f;
    if (i < N_NODES * HEADS) g_norm[i] = 0.0f;
}

// ---------------------------------------------------------------------------
// Fused QKV projection. 768 threads: group m = t>>8 handles matrix m
// (0=Q, 1=K, 2=V); within a group, thread tt computes 16 output cols
// [(tt&3)*16, +16) for node tt>>2 of a 64-node tile. E tile in smem shared
// by all three groups. Inner loop: 1 LDS + 4 LDS.128 + 8 FFMA2 per k.
// ---------------------------------------------------------------------------
__global__ __launch_bounds__(768) void gemm_qkv(
    const float* __restrict__ E,
    const float* __restrict__ Wq, const float* __restrict__ Wk,
    const float* __restrict__ Wv)
{
    __shared__ float4 sW4[3][1024];   // 3 x 64x64 W matrices
    __shared__ float  sE[64 * 68];    // 64-node tile, padded rows

    int t  = threadIdx.x;
    int m  = t >> 8;        // matrix id, uniform per warp
    int tt = t & 255;

    // Load this group's W (float4, coalesced)
    const float4* Wsrc = (m == 0) ? (const float4*)Wq
                       : (m == 1) ? (const float4*)Wk : (const float4*)Wv;
    #pragma unroll
    for (int i = 0; i < 4; i++) sW4[m][tt + i * 256] = Wsrc[tt + i * 256];

    // Load E tile (all 768 threads)
    int base = blockIdx.x * 64;
    for (int i = t; i < 4096; i += 768) {
        int r = i >> 6, c = i & 63;
        int node = base + r;
        sE[r * 68 + c] = (node < N_NODES) ? E[node * 64 + c] : 0.0f;
    }
    __syncthreads();

    int nl = tt >> 2;            // node within tile
    int qd = (tt & 3) * 16;      // output col quadrant
    const float* sWm = (const float*)sW4[m];

    u64 acc[8];
    #pragma unroll
    for (int j = 0; j < 8; j++) acc[j] = 0ull;

    #pragma unroll 4
    for (int k = 0; k < 64; k++) {
        u64 e2 = pack2(sE[nl * 68 + k]);
        const ulonglong2* w = (const ulonglong2*)(sWm + k * 64 + qd);
        #pragma unroll
        for (int j = 0; j < 4; j++) {
            ulonglong2 ww = w[j];               // LDS.128: W[k][qd+4j .. +3]
            acc[2 * j]     = ffma2(e2, ww.x, acc[2 * j]);
            acc[2 * j + 1] = ffma2(e2, ww.y, acc[2 * j + 1]);
        }
    }

    int node = base + nl;
    if (node < N_NODES) {
        float* O = (m == 0) ? g_Q : (m == 1) ? g_K : g_V;
        float4* o = (float4*)(O + node * 64 + qd);
        #pragma unroll
        for (int j = 0; j < 4; j++) {
            u64 a0 = acc[2 * j], a1 = acc[2 * j + 1];
            o[j] = make_float4(__uint_as_float((u32)a0),
                               __uint_as_float((u32)(a0 >> 32)),
                               __uint_as_float((u32)a1),
                               __uint_as_float((u32)(a1 >> 32)));
        }
    }
}

// ---------------------------------------------------------------------------
// Pass 1: expAtt[e,h] = exp(clip(q·k, -10, 10)); accumulate segment norms.
// ---------------------------------------------------------------------------
__global__ void edge_logits(const int* __restrict__ rows, const int* __restrict__ cols,
                            float* __restrict__ att) {
    int idx = blockIdx.x * blockDim.x + threadIdx.x;
    if (idx >= N_EDGES * HEADS) return;
    int e = idx >> 2, h = idx & 3;
    int r = rows[e], c = cols[e];

    const float4* q = (const float4*)(g_Q + r * DIM + h * DH);
    const float4* k = (const float4*)(g_K + c * DIM + h * DH);

    float s = 0.0f;
    #pragma unroll
    for (int i = 0; i < 4; i++) {
        float4 a = q[i], b = k[i];
        s += a.x * b.x + a.y * b.y + a.z * b.z + a.w * b.w;
    }
    s = fminf(fmaxf(s, -10.0f), 10.0f);
    float ex = expf(s);

    att[idx] = ex;                               // staged; normalized in pass 2
    atomicAdd(&g_norm[r * HEADS + h], ex);
}

// ---------------------------------------------------------------------------
// Vector reduction (no return): 1 L2 transaction for 4 floats.
// ---------------------------------------------------------------------------
__device__ __forceinline__ void red_add_v4(float* addr, float a, float b,
                                           float c, float d) {
    asm volatile("red.global.add.v4.f32 [%0], {%1, %2, %3, %4};"
                 :: "l"(addr), "f"(a), "f"(b), "f"(c), "f"(d)
                 : "memory");
}

// ---------------------------------------------------------------------------
// Pass 2: att = expAtt / (norm[row] + eps); res[row] += att * V[col].
// ---------------------------------------------------------------------------
__global__ void edge_accum(const int* __restrict__ rows, const int* __restrict__ cols,
                           float* __restrict__ res, float* __restrict__ att) {
    int idx = blockIdx.x * blockDim.x + threadIdx.x;
    if (idx >= N_EDGES * HEADS) return;
    int e = idx >> 2, h = idx & 3;
    int r = rows[e], c = cols[e];

    float ex = att[idx];
    float a  = ex / (g_norm[r * HEADS + h] + 1e-8f);
    att[idx] = a;

    const float4* v = (const float4*)(g_V + c * DIM + h * DH);
    float* dst = res + r * DIM + h * DH;
    #pragma unroll
    for (int i = 0; i < 4; i++) {
        float4 vv = v[i];
        red_add_v4(dst + i * 4, a * vv.x, a * vv.y, a * vv.z, a * vv.w);
    }
}

// ---------------------------------------------------------------------------
extern "C" void kernel_launch(void* const* d_in, const int* in_sizes, int n_in,
                              void* d_out, int out_size) {
    const float* embeds = (const float*)d_in[0];
    const float* Wq     = (const float*)d_in[1];
    const float* Wk     = (const float*)d_in[2];
    const float* Wv     = (const float*)d_in[3];
    const int*   rows   = (const int*)d_in[4];
    const int*   cols   = (const int*)d_in[5];

    float* res = (float*)d_out;                    // [N_NODES, 64]
    float* att = (float*)d_out + N_NODES * DIM;    // [N_EDGES, 4]

    // 1) zero res + norm
    zero_kernel<<<(N_NODES * DIM + 255) / 256, 256>>>(res);

    // 2) fused QKV projection (per node)
    int gemm_blocks = (N_NODES + 63) / 64;
    gemm_qkv<<<gemm_blocks, 768>>>(embeds, Wq, Wk, Wv);

    // 3) logits + segment norm
    int edge_blocks = (N_EDGES * HEADS + 255) / 256;
    edge_logits<<<edge_blocks, 256>>>(rows, cols, att);

    // 4) normalize + scatter-accumulate
    edge_accum<<<edge_blocks, 256>>>(rows, cols, res, att);
}

// round 3
// speedup vs baseline: 2.1862x; 2.0637x over previous
#include <cuda_runtime.h>

#define N_NODES 100000
#define N_EDGES 800000
#define DIM     64
#define HEADS   4
#define DH      16

typedef unsigned long long u64;
typedef unsigned int       u32;

// L2-resident scratch (GB300 L2 ~126MB; Q+K+V = 76.8MB)
__device__ float g_Q[N_NODES * DIM];
__device__ float g_K[N_NODES * DIM];
__device__ float g_V[N_NODES * DIM];
__device__ float g_norm[N_NODES * HEADS];

// ---------------------------------------------------------------------------
// Packed fp32x2 FMA (Blackwell FFMA2).
// ---------------------------------------------------------------------------
__device__ __forceinline__ u64 ffma2(u64 a, u64 b, u64 c) {
    u64 d;
    asm("fma.rn.f32x2 %0, %1, %2, %3;" : "=l"(d) : "l"(a), "l"(b), "l"(c));
    return d;
}
__device__ __forceinline__ u64 pack2(float x) {
    u64 r; u32 xi = __float_as_uint(x);
    asm("mov.b64 %0, {%1, %1};" : "=l"(r) : "r"(xi));
    return r;
}

// ---------------------------------------------------------------------------
// Register-blocked fused QKV GEMM.
// Block: 256 threads, 256-node tile, loops over the 3 weight matrices
// reusing the smem E tile. Thread (tx = t&7, ty = t>>3) computes an
// 8-node x 8-col register tile: per k, 8 scalar LDS (A, broadcast across tx)
// + 2 LDS.128 (B, broadcast across ty) + 32 FFMA2 on 32 independent u64 accs.
// Dynamic smem: sE[256][65] (66560B, pad 65 -> conflict-free strided reads)
// + sW[64][64] (16384B) = 82944B -> 2 blocks/SM.
// ---------------------------------------------------------------------------
__global__ __launch_bounds__(256, 2) void gemm_qkv(
    const float* __restrict__ E,
    const float* __restrict__ Wq, const float* __restrict__ Wk,
    const float* __restrict__ Wv)
{
    extern __shared__ float sh[];
    float* sE = sh;                // [256][65]
    float* sW = sh + 256 * 65;     // [64][64]

    int t    = threadIdx.x;
    int base = blockIdx.x * 256;

    // Load E tile (float4 global reads, scalar smem stores due to pad-65 rows)
    for (int i = t; i < 4096; i += 256) {
        int r  = i >> 4;            // row in tile (16 float4 per 64-float row)
        int c4 = i & 15;
        int node = base + r;
        float4 v = (node < N_NODES) ? ((const float4*)E)[node * 16 + c4]
                                    : make_float4(0.f, 0.f, 0.f, 0.f);
        float* d = &sE[r * 65 + c4 * 4];
        d[0] = v.x; d[1] = v.y; d[2] = v.z; d[3] = v.w;
    }

    int tx = t & 7, ty = t >> 3;
    int c0 = tx * 8;                // 8 output cols
    int n0 = ty * 8;                // 8 nodes

    #pragma unroll
    for (int m = 0; m < 3; m++) {
        if (m > 0) __syncthreads();          // sW reads from prev iter done
        const float4* Wsrc = (m == 0) ? (const float4*)Wq
                           : (m == 1) ? (const float4*)Wk : (const float4*)Wv;
        #pragma unroll
        for (int i = 0; i < 4; i++)
            ((float4*)sW)[t + i * 256] = Wsrc[t + i * 256];
        __syncthreads();                     // also covers sE fill when m==0

        u64 acc[8][4];
        #pragma unroll
        for (int i = 0; i < 8; i++)
            #pragma unroll
            for (int j = 0; j < 4; j++) acc[i][j] = 0ull;

        #pragma unroll 4
        for (int k = 0; k < 64; k++) {
            ulonglong2 b0 = *(const ulonglong2*)&sW[k * 64 + c0];
            ulonglong2 b1 = *(const ulonglong2*)&sW[k * 64 + c0 + 4];
            #pragma unroll
            for (int i = 0; i < 8; i++) {
                u64 a2 = pack2(sE[(n0 + i) * 65 + k]);
                acc[i][0] = ffma2(a2, b0.x, acc[i][0]);
                acc[i][1] = ffma2(a2, b0.y, acc[i][1]);
                acc[i][2] = ffma2(a2, b1.x, acc[i][2]);
                acc[i][3] = ffma2(a2, b1.y, acc[i][3]);
            }
        }

        float* O = (m == 0) ? g_Q : (m == 1) ? g_K : g_V;
        #pragma unroll
        for (int i = 0; i < 8; i++) {
            int node = base + n0 + i;
            if (node < N_NODES) {
                float4* o = (float4*)(O + node * 64 + c0);
                u64 a0 = acc[i][0], a1 = acc[i][1];
                u64 a2 = acc[i][2], a3 = acc[i][3];
                o[0] = make_float4(__uint_as_float((u32)a0),
                                   __uint_as_float((u32)(a0 >> 32)),
                                   __uint_as_float((u32)a1),
                                   __uint_as_float((u32)(a1 >> 32)));
                o[1] = make_float4(__uint_as_float((u32)a2),
                                   __uint_as_float((u32)(a2 >> 32)),
                                   __uint_as_float((u32)a3),
                                   __uint_as_float((u32)(a3 >> 32)));
            }
        }
    }
}

// ---------------------------------------------------------------------------
// Pass 1: expAtt[e,h] = exp(clip(q.k, -10, 10)); accumulate segment norms.
// ---------------------------------------------------------------------------
__global__ void edge_logits(const int* __restrict__ rows, const int* __restrict__ cols,
                            float* __restrict__ att) {
    int idx = blockIdx.x * blockDim.x + threadIdx.x;
    if (idx >= N_EDGES * HEADS) return;
    int e = idx >> 2, h = idx & 3;
    int r = rows[e], c = cols[e];

    const float4* q = (const float4*)(g_Q + r * DIM + h * DH);
    const float4* k = (const float4*)(g_K + c * DIM + h * DH);

    float s = 0.0f;
    #pragma unroll
    for (int i = 0; i < 4; i++) {
        float4 a = q[i], b = k[i];
        s += a.x * b.x + a.y * b.y + a.z * b.z + a.w * b.w;
    }
    s = fminf(fmaxf(s, -10.0f), 10.0f);
    float ex = __expf(s);

    att[idx] = ex;                               // staged; normalized in pass 2
    atomicAdd(&g_norm[r * HEADS + h], ex);
}

// ---------------------------------------------------------------------------
// Vector reduction (no return): 1 L2 transaction for 4 floats.
// ---------------------------------------------------------------------------
__device__ __forceinline__ void red_add_v4(float* addr, float a, float b,
                                           float c, float d) {
    asm volatile("red.global.add.v4.f32 [%0], {%1, %2, %3, %4};"
                 :: "l"(addr), "f"(a), "f"(b), "f"(c), "f"(d)
                 : "memory");
}

// ---------------------------------------------------------------------------
// Pass 2: att = expAtt / (norm[row] + eps); res[row] += att * V[col].
// ---------------------------------------------------------------------------
__global__ void edge_accum(const int* __restrict__ rows, const int* __restrict__ cols,
                           float* __restrict__ res, float* __restrict__ att) {
    int idx = blockIdx.x * blockDim.x + threadIdx.x;
    if (idx >= N_EDGES * HEADS) return;
    int e = idx >> 2, h = idx & 3;
    int r = rows[e], c = cols[e];

    float ex = att[idx];
    float a  = ex / (g_norm[r * HEADS + h] + 1e-8f);
    att[idx] = a;

    const float4* v = (const float4*)(g_V + c * DIM + h * DH);
    float* dst = res + r * DIM + h * DH;
    #pragma unroll
    for (int i = 0; i < 4; i++) {
        float4 vv = v[i];
        red_add_v4(dst + i * 4, a * vv.x, a * vv.y, a * vv.z, a * vv.w);
    }
}

// ---------------------------------------------------------------------------
extern "C" void kernel_launch(void* const* d_in, const int* in_sizes, int n_in,
                              void* d_out, int out_size) {
    const float* embeds = (const float*)d_in[0];
    const float* Wq     = (const float*)d_in[1];
    const float* Wk     = (const float*)d_in[2];
    const float* Wv     = (const float*)d_in[3];
    const int*   rows   = (const int*)d_in[4];
    const int*   cols   = (const int*)d_in[5];

    float* res = (float*)d_out;                    // [N_NODES, 64]
    float* att = (float*)d_out + N_NODES * DIM;    // [N_EDGES, 4]

    // 1) zero res + norm (memsets are graph-capturable)
    void* pNorm;
    cudaGetSymbolAddress(&pNorm, g_norm);
    cudaMemsetAsync(res, 0, (size_t)N_NODES * DIM * sizeof(float));
    cudaMemsetAsync(pNorm, 0, (size_t)N_NODES * HEADS * sizeof(float));

    // 2) fused register-blocked QKV projection
    const int smem_bytes = (256 * 65 + 64 * 64) * sizeof(float);   // 82944
    cudaFuncSetAttribute(gemm_qkv, cudaFuncAttributeMaxDynamicSharedMemorySize,
                         smem_bytes);
    int gemm_blocks = (N_NODES + 255) / 256;
    gemm_qkv<<<gemm_blocks, 256, smem_bytes>>>(embeds, Wq, Wk, Wv);

    // 3) logits + segment norm
    int edge_blocks = (N_EDGES * HEADS + 255) / 256;
    edge_logits<<<edge_blocks, 256>>>(rows, cols, att);

    // 4) normalize + scatter-accumulate
    edge_accum<<<edge_blocks, 256>>>(rows, cols, res, att);
}